// round 14
// baseline (speedup 1.0000x reference)
#include <cuda_runtime.h>
#include <cuda_fp16.h>
#include <cstdint>

#define VOCAB 10000
#define EMBED 100
#define SEQ   80
#define UNITS 64
#define BATCH 16384
#define MROWS 128          // batch rows per CTA (4 warps x 2 tiles x 16 rows)
#define XSB   144          // xs row stride BYTES (conflict-free init)
#define TKS   81           // token smem row stride (ints)

// xproj[v][u] = b1[u] + emb[v,:] @ Wx1[:,u]   (f16, 1.28 MB, L2-resident)
__device__ __half g_xproj_h[VOCAB * UNITS];

// ---------------------------------------------------------------------------
// helpers
// ---------------------------------------------------------------------------
__device__ __forceinline__ uint32_t smem_u32(const void* p) {
    uint32_t a;
    asm("{ .reg .u64 t; cvta.to.shared.u64 t, %1; cvt.u32.u64 %0, t; }" : "=r"(a) : "l"(p));
    return a;
}
#define SWZ(off) ((uint32_t)(off) ^ ((((uint32_t)(off)) >> 3) & 0x70))

__device__ __forceinline__ uint32_t pack_f16(float lo, float hi) {
    uint32_t r; asm("cvt.rn.f16x2.f32 %0, %1, %2;" : "=r"(r) : "f"(hi), "f"(lo)); return r;
}
__device__ __forceinline__ uint32_t tanh2(uint32_t x) {
    uint32_t r; asm("tanh.approx.f16x2 %0, %1;" : "=r"(r) : "r"(x)); return r;
}
__device__ __forceinline__ float2 unpk_f16(uint32_t u) {
    __half2 h = *reinterpret_cast<__half2*>(&u);
    return __half22float2(h);
}

#define LDSM_X4(r0, r1, r2, r3, addr)                                       \
    asm volatile("ldmatrix.sync.aligned.m8n8.x4.shared.b16 {%0,%1,%2,%3}, [%4];" \
                 : "=r"(r0), "=r"(r1), "=r"(r2), "=r"(r3) : "r"(addr))

// f16 C/D MMA: D-frag (2 regs) is already A-frag-layout f16x2. Non-volatile.
#define MMA_F16C(ac, A, b0, b1)                                             \
    asm("mma.sync.aligned.m16n8k16.row.col.f16.f16.f16.f16 "                \
        "{%0,%1}, {%2,%3,%4,%5}, {%6,%7}, {%0,%1};"                         \
        : "+r"((ac)[0]), "+r"((ac)[1])                                      \
        : "r"((A)[0]), "r"((A)[1]), "r"((A)[2]), "r"((A)[3]),               \
          "r"(b0), "r"(b1))

#define CP_ASYNC_4(dst, src)                                                \
    asm volatile("cp.async.ca.shared.global [%0], [%1], 4;"                 \
                 :: "r"(dst), "l"(src) : "memory")
#define CP_COMMIT()  asm volatile("cp.async.commit_group;" ::: "memory")
#define CP_WAIT1()   asm volatile("cp.async.wait_group 1;" ::: "memory")
#define CP_WAIT0()   asm volatile("cp.async.wait_group 0;" ::: "memory")

// ---------------------------------------------------------------------------
// Kernel A: build xproj table (f16 output)
// ---------------------------------------------------------------------------
__global__ void build_xproj_kernel(const float* __restrict__ emb,
                                   const float* __restrict__ Wx1,
                                   const float* __restrict__ b1) {
    __shared__ float se[4 * EMBED];
    const int v0  = blockIdx.x * 4;
    const int tid = threadIdx.x;
    for (int i = tid; i < 4 * EMBED; i += 256)
        se[i] = emb[v0 * EMBED + i];
    __syncthreads();
    const int vl = tid >> 6;
    const int u  = tid & 63;
    const float* er = se + vl * EMBED;
    float a0 = 0.f, a1 = 0.f;
#pragma unroll
    for (int e = 0; e < EMBED; e += 2) {
        a0 += er[e]     * Wx1[e * UNITS + u];
        a1 += er[e + 1] * Wx1[(e + 1) * UNITS + u];
    }
    g_xproj_h[(v0 + vl) * UNITS + u] = __float2half(b1[u] + a0 + a1);
}

// ---------------------------------------------------------------------------
// smem layout (byte offsets from 1024-aligned base)
// ---------------------------------------------------------------------------
#define OFF_W1   0                                  // Wh1^T [n][k] f16 SW128, 8KB
#define OFF_W2   8192                               // Wh2^T [n][k] f16 SW128, 8KB
#define OFF_XS0  16384                              // xs buf 0: 128 rows x 144B
#define OFF_XS1  (OFF_XS0 + MROWS * XSB)
#define OFF_TOK  (OFF_XS1 + MROWS * XSB)            // 128 x 81 int
#define OFF_WD   (OFF_TOK + MROWS * TKS * 4)
#define SMEM_NEED (OFF_WD + 256 + 1024)

// ---------------------------------------------------------------------------
// Kernel B: 4 warps (1/SMSP) x 2 independent 16-row tiles each.
// In-warp ILP replaces cross-warp hiding. Wh1+Wh2 streamed (amortized over
// both tiles), Wx2 persistent in regs (latency-critical gemm2b chain).
// ---------------------------------------------------------------------------
__global__ void __launch_bounds__(128, 1)
rnn_mma_kernel(const int*   __restrict__ tokens,
               const float* __restrict__ Wh1,
               const float* __restrict__ Wx2,
               const float* __restrict__ Wh2,
               const float* __restrict__ b2,
               const float* __restrict__ Wd,
               const float* __restrict__ bd,
               float*       __restrict__ out) {
    extern __shared__ char dynsmem[];
    char* smem = (char*)(((uintptr_t)dynsmem + 1023) & ~(uintptr_t)1023);
    const uint32_t sb = smem_u32(smem);
    int*   stok = (int*)(smem + OFF_TOK);
    float* sWd  = (float*)(smem + OFF_WD);

    const int tid  = threadIdx.x;
    const int lane = tid & 31;
    const int wid  = tid >> 5;           // 0..3
    const int gid  = lane >> 2;
    const int tig  = lane & 3;
    const int wrow32 = wid * 32;         // warp's 32 rows (2 tiles)
    const int m0   = blockIdx.x * MROWS;

    // ---- persistent Wx2 B-fragments + b2 ----
    uint32_t BX2[8][4][2];
#pragma unroll
    for (int nt = 0; nt < 8; nt++)
#pragma unroll
        for (int kt = 0; kt < 4; kt++) {
            const int n = nt * 8 + gid;
            const int k = kt * 16 + tig * 2;
            BX2[nt][kt][0] = pack_f16(Wx2[k * 64 + n],       Wx2[(k + 1) * 64 + n]);
            BX2[nt][kt][1] = pack_f16(Wx2[(k + 8) * 64 + n], Wx2[(k + 9) * 64 + n]);
        }
    uint32_t b2v[8];
#pragma unroll
    for (int nt = 0; nt < 8; nt++)
        b2v[nt] = pack_f16(b2[nt * 8 + tig * 2], b2[nt * 8 + tig * 2 + 1]);

    // ---- init smem: Wh1^T / Wh2^T tiles [n][k] f16 SW128, tokens, Wd ----
    for (int i = tid; i < UNITS * UNITS; i += 128) {
        int n = i >> 6, k = i & 63;
        uint32_t so = SWZ(n * 128 + k * 2);
        *(__half*)(smem + OFF_W1 + so) = __float2half(Wh1[k * 64 + n]);
        *(__half*)(smem + OFF_W2 + so) = __float2half(Wh2[k * 64 + n]);
    }
    {
        const int* gtok = tokens + m0 * SEQ;
        for (int i = tid; i < MROWS * SEQ; i += 128)
            stok[(i / SEQ) * TKS + (i % SEQ)] = gtok[i];
    }
    if (tid < UNITS) sWd[tid] = Wd[tid];
    __syncthreads();

    const uint32_t w1Base = sb + OFF_W1;
    const uint32_t w2Base = sb + OFF_W2;
    const uint32_t bRow = (uint32_t)((((lane >> 4) << 3) | (lane & 7)));
    const uint32_t bKo  = (uint32_t)(((lane >> 3) & 1) << 3);
    const uint32_t xsLaneOff = (uint32_t)(wrow32 * XSB) + (uint32_t)(lane * 4);

    // h fragments per tile (A-frag layout, f16x2), h0 = 0
    uint32_t h1f[2][4][4], h2f[2][4][4];
#pragma unroll
    for (int u = 0; u < 2; u++)
#pragma unroll
        for (int kt = 0; kt < 4; kt++)
#pragma unroll
            for (int j = 0; j < 4; j++) { h1f[u][kt][j] = 0u; h2f[u][kt][j] = 0u; }

    uint32_t acc1[2][8][2], acc2[2][8][2];   // f16x2 accumulators per tile

    // ---- prime gather: step 0 (32 rows, 1 row per lane-token) ----
    {
        const int tokreg = stok[(wrow32 + lane) * TKS + 0];
        const uint32_t dst = sb + OFF_XS0 + xsLaneOff;
#pragma unroll
        for (int r = 0; r < 32; r++) {
            const int tok = __shfl_sync(0xffffffffu, tokreg, r);
            CP_ASYNC_4(dst + (uint32_t)(r * XSB), g_xproj_h + tok * UNITS + lane * 2);
        }
        CP_COMMIT();
    }

    for (int t = 0; t < SEQ; t++) {
        const uint32_t xsOff = (t & 1) ? OFF_XS1 : OFF_XS0;

        // ---- prefetch gather for t+1; wait for step t's rows ----
        if (t + 1 < SEQ) {
            const int tokreg = stok[(wrow32 + lane) * TKS + (t + 1)];
            const uint32_t dst = sb + (((t + 1) & 1) ? OFF_XS1 : OFF_XS0) + xsLaneOff;
#pragma unroll
            for (int r = 0; r < 32; r++) {
                const int tok = __shfl_sync(0xffffffffu, tokreg, r);
                CP_ASYNC_4(dst + (uint32_t)(r * XSB), g_xproj_h + tok * UNITS + lane * 2);
            }
            CP_COMMIT();
            CP_WAIT1();
        } else {
            CP_WAIT0();
        }

        // ---- init: acc1[u] = xproj(t) (conflict-free LDS), acc2[u] = b2 ----
#pragma unroll
        for (int u = 0; u < 2; u++) {
            const char* xrow0 = smem + xsOff + (wrow32 + u * 16 + gid) * XSB + tig * 4;
#pragma unroll
            for (int nt = 0; nt < 8; nt++) {
                acc1[u][nt][0] = *(const uint32_t*)(xrow0 + nt * 16);
                acc1[u][nt][1] = *(const uint32_t*)(xrow0 + 8 * XSB + nt * 16);
                acc2[u][nt][0] = b2v[nt];
                acc2[u][nt][1] = b2v[nt];
            }
        }

        // ---- gemm2a: acc2[u] += h2[u] @ Wh2 (streamed, shared by tiles) ----
#pragma unroll
        for (int kt = 0; kt < 4; kt++) {
            uint32_t Bs[4][4];
#pragma unroll
            for (int np = 0; np < 4; np++)
                LDSM_X4(Bs[np][0], Bs[np][1], Bs[np][2], Bs[np][3],
                        w2Base + SWZ((np * 16 + bRow) * 128 + (kt * 16 + bKo) * 2));
#pragma unroll
            for (int u = 0; u < 2; u++)
#pragma unroll
                for (int np = 0; np < 4; np++) {
                    MMA_F16C(acc2[u][2 * np],     h2f[u][kt], Bs[np][0], Bs[np][1]);
                    MMA_F16C(acc2[u][2 * np + 1], h2f[u][kt], Bs[np][2], Bs[np][3]);
                }
        }

        // ---- gemm1: acc1[u] += h1[u] @ Wh1 (streamed, shared by tiles) ----
#pragma unroll
        for (int kt = 0; kt < 4; kt++) {
            uint32_t Bs[4][4];
#pragma unroll
            for (int np = 0; np < 4; np++)
                LDSM_X4(Bs[np][0], Bs[np][1], Bs[np][2], Bs[np][3],
                        w1Base + SWZ((np * 16 + bRow) * 128 + (kt * 16 + bKo) * 2));
#pragma unroll
            for (int u = 0; u < 2; u++)
#pragma unroll
                for (int np = 0; np < 4; np++) {
                    MMA_F16C(acc1[u][2 * np],     h1f[u][kt], Bs[np][0], Bs[np][1]);
                    MMA_F16C(acc1[u][2 * np + 1], h1f[u][kt], Bs[np][2], Bs[np][3]);
                }
        }

        // ---- epi1: h1[u] = tanh2(acc1[u]) — acc IS the next A-frag ----
#pragma unroll
        for (int u = 0; u < 2; u++)
#pragma unroll
            for (int nt = 0; nt < 8; nt++) {
                h1f[u][nt >> 1][(nt & 1) * 2 + 0] = tanh2(acc1[u][nt][0]);
                h1f[u][nt >> 1][(nt & 1) * 2 + 1] = tanh2(acc1[u][nt][1]);
            }

        // ---- gemm2b: acc2[u] += h1[u] @ Wx2 (register B-frags) ----
#pragma unroll
        for (int kt = 0; kt < 4; kt++)
#pragma unroll
            for (int u = 0; u < 2; u++)
#pragma unroll
                for (int nt = 0; nt < 8; nt++)
                    MMA_F16C(acc2[u][nt], h1f[u][kt], BX2[nt][kt][0], BX2[nt][kt][1]);

        // ---- epi2: h2[u] = tanh2(acc2[u]) ----
#pragma unroll
        for (int u = 0; u < 2; u++)
#pragma unroll
            for (int nt = 0; nt < 8; nt++) {
                h2f[u][nt >> 1][(nt & 1) * 2 + 0] = tanh2(acc2[u][nt][0]);
                h2f[u][nt >> 1][(nt & 1) * 2 + 1] = tanh2(acc2[u][nt][1]);
            }
    }

    // ---- head: out = sigmoid(h2 . Wd + bd); reduce over tig group ----
#pragma unroll
    for (int u = 0; u < 2; u++) {
        float z0 = 0.f, z1 = 0.f;
#pragma unroll
        for (int nt = 0; nt < 8; nt++) {
            const int col = nt * 8 + tig * 2;
            float2 wd = *(const float2*)(sWd + col);
            float2 a = unpk_f16(h2f[u][nt >> 1][(nt & 1) * 2 + 0]);   // row gid
            float2 b = unpk_f16(h2f[u][nt >> 1][(nt & 1) * 2 + 1]);   // row gid+8
            z0 += a.x * wd.x + a.y * wd.y;
            z1 += b.x * wd.x + b.y * wd.y;
        }
        z0 += __shfl_xor_sync(0xffffffffu, z0, 1);
        z0 += __shfl_xor_sync(0xffffffffu, z0, 2);
        z1 += __shfl_xor_sync(0xffffffffu, z1, 1);
        z1 += __shfl_xor_sync(0xffffffffu, z1, 2);
        if (tig == 0) {
            const float bd0 = bd[0];
            const int row = m0 + wrow32 + u * 16 + gid;
            out[row]     = 1.0f / (1.0f + __expf(-(z0 + bd0)));
            out[row + 8] = 1.0f / (1.0f + __expf(-(z1 + bd0)));
        }
    }
}

// ---------------------------------------------------------------------------
extern "C" void kernel_launch(void* const* d_in, const int* in_sizes, int n_in,
                              void* d_out, int out_size) {
    const int*   tokens = (const int*)  d_in[0];
    const float* emb    = (const float*)d_in[1];
    const float* Wx1    = (const float*)d_in[2];
    const float* Wh1    = (const float*)d_in[3];
    const float* b1     = (const float*)d_in[4];
    const float* Wx2    = (const float*)d_in[5];
    const float* Wh2    = (const float*)d_in[6];
    const float* b2     = (const float*)d_in[7];
    const float* Wd     = (const float*)d_in[8];
    const float* bd     = (const float*)d_in[9];
    float* out = (float*)d_out;

    build_xproj_kernel<<<VOCAB / 4, 256>>>(emb, Wx1, b1);

    cudaFuncSetAttribute(rnn_mma_kernel,
                         cudaFuncAttributeMaxDynamicSharedMemorySize, SMEM_NEED);
    rnn_mma_kernel<<<BATCH / MROWS, 128, SMEM_NEED>>>(
        tokens, Wh1, Wx2, Wh2, b2, Wd, bd, out);
}

// round 15
// speedup vs baseline: 1.2302x; 1.2302x over previous
#include <cuda_runtime.h>
#include <cuda_fp16.h>
#include <cstdint>

#define VOCAB 10000
#define EMBED 100
#define SEQ   80
#define UNITS 64
#define BATCH 16384
#define MROWS 128          // batch rows per CTA
#define XSB   144          // xs row stride BYTES (conflict-free init)
#define TKS   81           // token smem row stride (ints)

// xproj[v][u] = b1[u] + emb[v,:] @ Wx1[:,u]   (f16, 1.28 MB, L2-resident)
__device__ __half g_xproj_h[VOCAB * UNITS];

// ---------------------------------------------------------------------------
// helpers
// ---------------------------------------------------------------------------
__device__ __forceinline__ uint32_t smem_u32(const void* p) {
    uint32_t a;
    asm("{ .reg .u64 t; cvta.to.shared.u64 t, %1; cvt.u32.u64 %0, t; }" : "=r"(a) : "l"(p));
    return a;
}
#define SWZ(off) ((uint32_t)(off) ^ ((((uint32_t)(off)) >> 3) & 0x70))

__device__ __forceinline__ uint32_t pack_f16(float lo, float hi) {
    uint32_t r; asm("cvt.rn.f16x2.f32 %0, %1, %2;" : "=r"(r) : "f"(hi), "f"(lo)); return r;
}
__device__ __forceinline__ uint32_t tanh2(uint32_t x) {
    uint32_t r; asm("tanh.approx.f16x2 %0, %1;" : "=r"(r) : "r"(x)); return r;
}
__device__ __forceinline__ float2 unpk_f16(uint32_t u) {
    __half2 h = *reinterpret_cast<__half2*>(&u);
    return __half22float2(h);
}

// LDSM: volatile (pins ordering) but no memory clobber.
#define LDSM_X4(r0, r1, r2, r3, addr)                                       \
    asm volatile("ldmatrix.sync.aligned.m8n8.x4.shared.b16 {%0,%1,%2,%3}, [%4];" \
                 : "=r"(r0), "=r"(r1), "=r"(r2), "=r"(r3) : "r"(addr))

// f16 C/D MMA, accumulate in place. Non-volatile pure register op.
#define MMA_F16C(ac, A, b0, b1)                                             \
    asm("mma.sync.aligned.m16n8k16.row.col.f16.f16.f16.f16 "                \
        "{%0,%1}, {%2,%3,%4,%5}, {%6,%7}, {%0,%1};"                         \
        : "+r"((ac)[0]), "+r"((ac)[1])                                      \
        : "r"((A)[0]), "r"((A)[1]), "r"((A)[2]), "r"((A)[3]),               \
          "r"(b0), "r"(b1))

// f16 C/D MMA, separate C operand (init form): D = A*B + {c0,c1}
#define MMA_F16C_INIT(ac, A, b0, b1, c0, c1)                                \
    asm("mma.sync.aligned.m16n8k16.row.col.f16.f16.f16.f16 "                \
        "{%0,%1}, {%2,%3,%4,%5}, {%6,%7}, {%8,%9};"                         \
        : "=r"((ac)[0]), "=r"((ac)[1])                                      \
        : "r"((A)[0]), "r"((A)[1]), "r"((A)[2]), "r"((A)[3]),               \
          "r"(b0), "r"(b1), "r"(c0), "r"(c1))

#define CP_ASYNC_4(dst, src)                                                \
    asm volatile("cp.async.ca.shared.global [%0], [%1], 4;"                 \
                 :: "r"(dst), "l"(src) : "memory")
#define CP_COMMIT()  asm volatile("cp.async.commit_group;" ::: "memory")
#define CP_WAIT1()   asm volatile("cp.async.wait_group 1;" ::: "memory")
#define CP_WAIT0()   asm volatile("cp.async.wait_group 0;" ::: "memory")

// ---------------------------------------------------------------------------
// Kernel A: build xproj table (f16 output)
// ---------------------------------------------------------------------------
__global__ void build_xproj_kernel(const float* __restrict__ emb,
                                   const float* __restrict__ Wx1,
                                   const float* __restrict__ b1) {
    __shared__ float se[4 * EMBED];
    const int v0  = blockIdx.x * 4;
    const int tid = threadIdx.x;
    for (int i = tid; i < 4 * EMBED; i += 256)
        se[i] = emb[v0 * EMBED + i];
    __syncthreads();
    const int vl = tid >> 6;
    const int u  = tid & 63;
    const float* er = se + vl * EMBED;
    float a0 = 0.f, a1 = 0.f;
#pragma unroll
    for (int e = 0; e < EMBED; e += 2) {
        a0 += er[e]     * Wx1[e * UNITS + u];
        a1 += er[e + 1] * Wx1[(e + 1) * UNITS + u];
    }
    g_xproj_h[(v0 + vl) * UNITS + u] = __float2half(b1[u] + a0 + a1);
}

// ---------------------------------------------------------------------------
// smem layout (byte offsets from 1024-aligned base)
// ---------------------------------------------------------------------------
#define OFF_W1   0                                  // Wh1^T [n][k] f16 SW128, 8KB
#define OFF_XS0  8192                               // xs buf 0: 128 rows x 144B (f16)
#define OFF_XS1  (OFF_XS0 + MROWS * XSB)
#define OFF_TOK  (OFF_XS1 + MROWS * XSB)            // 128 x 81 int
#define OFF_WD   (OFF_TOK + MROWS * TKS * 4)
#define SMEM_NEED (OFF_WD + 256 + 1024)

// ---------------------------------------------------------------------------
// Kernel B: 8 independent warps x 16 rows x 64 cols, full-f16 datapath.
// R12 structure; t-loop unrolled x2 so ptxas can overlap epi2(t) with
// gemm1(t+1) (which depends only on h1f(t)); acc2 init fused into kt=0 MMA.
// ---------------------------------------------------------------------------
__global__ void __launch_bounds__(256, 1)
rnn_mma_kernel(const int*   __restrict__ tokens,
               const float* __restrict__ Wh1,
               const float* __restrict__ Wx2,
               const float* __restrict__ Wh2,
               const float* __restrict__ b2,
               const float* __restrict__ Wd,
               const float* __restrict__ bd,
               float*       __restrict__ out) {
    extern __shared__ char dynsmem[];
    char* smem = (char*)(((uintptr_t)dynsmem + 1023) & ~(uintptr_t)1023);
    const uint32_t sb = smem_u32(smem);
    int*   stok = (int*)(smem + OFF_TOK);
    float* sWd  = (float*)(smem + OFF_WD);

    const int tid  = threadIdx.x;
    const int lane = tid & 31;
    const int wid  = tid >> 5;
    const int gid  = lane >> 2;
    const int tig  = lane & 3;
    const int wrow16 = wid * 16;
    const int m0   = blockIdx.x * MROWS;

    // ---- persistent B-fragments (full 64 cols, f16): [nt][kt][2] ----
    uint32_t BX2[8][4][2], BH2[8][4][2];
#pragma unroll
    for (int nt = 0; nt < 8; nt++)
#pragma unroll
        for (int kt = 0; kt < 4; kt++) {
            const int n = nt * 8 + gid;
            const int k = kt * 16 + tig * 2;
            BX2[nt][kt][0] = pack_f16(Wx2[k * 64 + n],       Wx2[(k + 1) * 64 + n]);
            BX2[nt][kt][1] = pack_f16(Wx2[(k + 8) * 64 + n], Wx2[(k + 9) * 64 + n]);
            BH2[nt][kt][0] = pack_f16(Wh2[k * 64 + n],       Wh2[(k + 1) * 64 + n]);
            BH2[nt][kt][1] = pack_f16(Wh2[(k + 8) * 64 + n], Wh2[(k + 9) * 64 + n]);
        }
    // persistent b2 f16x2 (same pair for row g and g+8)
    uint32_t b2v[8];
#pragma unroll
    for (int nt = 0; nt < 8; nt++)
        b2v[nt] = pack_f16(b2[nt * 8 + tig * 2], b2[nt * 8 + tig * 2 + 1]);

    // ---- init smem: Wh1^T tile [n][k] f16 SW128, tokens, Wd ----
    for (int i = tid; i < UNITS * UNITS; i += 256) {
        int n = i >> 6, k = i & 63;
        *(__half*)(smem + OFF_W1 + SWZ(n * 128 + k * 2)) =
            __float2half(Wh1[k * 64 + n]);
    }
    {
        const int* gtok = tokens + m0 * SEQ;
        for (int i = tid; i < MROWS * SEQ; i += 256)
            stok[(i / SEQ) * TKS + (i % SEQ)] = gtok[i];
    }
    if (tid < UNITS) sWd[tid] = Wd[tid];
    __syncthreads();

    const uint32_t w1Base = sb + OFF_W1;
    const uint32_t bRow = (uint32_t)((((lane >> 4) << 3) | (lane & 7)));
    const uint32_t bKo  = (uint32_t)(((lane >> 3) & 1) << 3);
    const uint32_t xsLaneOff = (uint32_t)(wrow16 * XSB) + (uint32_t)(lane * 4);

    // h fragments (A-frag layout, f16x2), h0 = 0
    uint32_t h1f[4][4], h2f[4][4];
#pragma unroll
    for (int kt = 0; kt < 4; kt++)
#pragma unroll
        for (int j = 0; j < 4; j++) { h1f[kt][j] = 0u; h2f[kt][j] = 0u; }

    uint32_t acc1[8][2], acc2[8][2];   // f16x2 accumulators

    // ---- prime gather pipeline: step 0 into buf 0 (4B/lane, 1 row/instr) ----
    {
        int tokreg = 0;
        if (lane < 16) tokreg = stok[(wrow16 + lane) * TKS + 0];
        const uint32_t dst = sb + OFF_XS0 + xsLaneOff;
#pragma unroll
        for (int r = 0; r < 16; r++) {
            const int tok = __shfl_sync(0xffffffffu, tokreg, r);
            CP_ASYNC_4(dst + (uint32_t)(r * XSB), g_xproj_h + tok * UNITS + lane * 2);
        }
        CP_COMMIT();
    }

#pragma unroll 2
    for (int t = 0; t < SEQ; t++) {
        const uint32_t xsOff = (t & 1) ? OFF_XS1 : OFF_XS0;

        // ---- prefetch gather for t+1; wait for step t's rows ----
        if (t + 1 < SEQ) {
            int tokreg = 0;
            if (lane < 16) tokreg = stok[(wrow16 + lane) * TKS + (t + 1)];
            const uint32_t dst = sb + (((t + 1) & 1) ? OFF_XS1 : OFF_XS0) + xsLaneOff;
#pragma unroll
            for (int r = 0; r < 16; r++) {
                const int tok = __shfl_sync(0xffffffffu, tokreg, r);
                CP_ASYNC_4(dst + (uint32_t)(r * XSB), g_xproj_h + tok * UNITS + lane * 2);
            }
            CP_COMMIT();
            CP_WAIT1();
        } else {
            CP_WAIT0();
        }

        // ---- init: acc1 = xproj(t) (f16x2 LDS, bank-conflict-free) ----
        {
            const char* xrow0 = smem + xsOff + (wrow16 + gid) * XSB + tig * 4;
#pragma unroll
            for (int nt = 0; nt < 8; nt++) {
                acc1[nt][0] = *(const uint32_t*)(xrow0 + nt * 16);
                acc1[nt][1] = *(const uint32_t*)(xrow0 + 8 * XSB + nt * 16);
            }
        }

        // ---- gemm1 (h1 @ Wh1, streamed B) interleaved with gemm2a (h2 @ Wh2);
        //      kt=0 of gemm2a initializes acc2 from b2 via the C operand ----
#pragma unroll
        for (int kt = 0; kt < 4; kt++) {
            uint32_t Bs[4][4];
#pragma unroll
            for (int np = 0; np < 4; np++)
                LDSM_X4(Bs[np][0], Bs[np][1], Bs[np][2], Bs[np][3],
                        w1Base + SWZ((np * 16 + bRow) * 128 + (kt * 16 + bKo) * 2));
            if (kt == 0) {
#pragma unroll
                for (int nt = 0; nt < 8; nt++)
                    MMA_F16C_INIT(acc2[nt], h2f[0], BH2[nt][0][0], BH2[nt][0][1],
                                  b2v[nt], b2v[nt]);
            } else {
#pragma unroll
                for (int nt = 0; nt < 8; nt++)
                    MMA_F16C(acc2[nt], h2f[kt], BH2[nt][kt][0], BH2[nt][kt][1]);
            }
#pragma unroll
            for (int np = 0; np < 4; np++) {
                MMA_F16C(acc1[2 * np],     h1f[kt], Bs[np][0], Bs[np][1]);
                MMA_F16C(acc1[2 * np + 1], h1f[kt], Bs[np][2], Bs[np][3]);
            }
        }

        // ---- epi1: h1 = tanh2(acc1) — accumulator IS the next A-frag ----
#pragma unroll
        for (int nt = 0; nt < 8; nt++) {
            h1f[nt >> 1][(nt & 1) * 2 + 0] = tanh2(acc1[nt][0]);
            h1f[nt >> 1][(nt & 1) * 2 + 1] = tanh2(acc1[nt][1]);
        }

        // ---- gemm2b: acc2 += h1_new @ Wx2 (all registers) ----
#pragma unroll
        for (int kt = 0; kt < 4; kt++)
#pragma unroll
            for (int nt = 0; nt < 8; nt++)
                MMA_F16C(acc2[nt], h1f[kt], BX2[nt][kt][0], BX2[nt][kt][1]);

        // ---- epi2: h2 = tanh2(acc2) ----
#pragma unroll
        for (int nt = 0; nt < 8; nt++) {
            h2f[nt >> 1][(nt & 1) * 2 + 0] = tanh2(acc2[nt][0]);
            h2f[nt >> 1][(nt & 1) * 2 + 1] = tanh2(acc2[nt][1]);
        }
    }

    // ---- head: out = sigmoid(h2 . Wd + bd); reduce over tig group ----
    float z0 = 0.f, z1 = 0.f;
#pragma unroll
    for (int nt = 0; nt < 8; nt++) {
        const int col = nt * 8 + tig * 2;
        float2 wd = *(const float2*)(sWd + col);
        float2 a = unpk_f16(h2f[nt >> 1][(nt & 1) * 2 + 0]);   // row gid
        float2 b = unpk_f16(h2f[nt >> 1][(nt & 1) * 2 + 1]);   // row gid+8
        z0 += a.x * wd.x + a.y * wd.y;
        z1 += b.x * wd.x + b.y * wd.y;
    }
    z0 += __shfl_xor_sync(0xffffffffu, z0, 1);
    z0 += __shfl_xor_sync(0xffffffffu, z0, 2);
    z1 += __shfl_xor_sync(0xffffffffu, z1, 1);
    z1 += __shfl_xor_sync(0xffffffffu, z1, 2);
    if (tig == 0) {
        const float bd0 = bd[0];
        out[m0 + wrow16 + gid]     = 1.0f / (1.0f + __expf(-(z0 + bd0)));
        out[m0 + wrow16 + gid + 8] = 1.0f / (1.0f + __expf(-(z1 + bd0)));
    }
}

// ---------------------------------------------------------------------------
extern "C" void kernel_launch(void* const* d_in, const int* in_sizes, int n_in,
                              void* d_out, int out_size) {
    const int*   tokens = (const int*)  d_in[0];
    const float* emb    = (const float*)d_in[1];
    const float* Wx1    = (const float*)d_in[2];
    const float* Wh1    = (const float*)d_in[3];
    const float* b1     = (const float*)d_in[4];
    const float* Wx2    = (const float*)d_in[5];
    const float* Wh2    = (const float*)d_in[6];
    const float* b2     = (const float*)d_in[7];
    const float* Wd     = (const float*)d_in[8];
    const float* bd     = (const float*)d_in[9];
    float* out = (float*)d_out;

    build_xproj_kernel<<<VOCAB / 4, 256>>>(emb, Wx1, b1);

    cudaFuncSetAttribute(rnn_mma_kernel,
                         cudaFuncAttributeMaxDynamicSharedMemorySize, SMEM_NEED);
    rnn_mma_kernel<<<BATCH / MROWS, 256, SMEM_NEED>>>(
        tokens, Wh1, Wx2, Wh2, b2, Wd, bd, out);
}

// round 16
// speedup vs baseline: 1.2324x; 1.0018x over previous
#include <cuda_runtime.h>
#include <cuda_fp16.h>
#include <cstdint>

#define VOCAB 10000
#define EMBED 100
#define SEQ   80
#define UNITS 64
#define BATCH 16384
#define MROWS 128          // batch rows per CTA
#define XSB   144          // xs row stride BYTES (conflict-free init)
#define TKS   81           // token smem row stride (ints)

// xproj[v][u] = b1[u] + emb[v,:] @ Wx1[:,u]   (f16, 1.28 MB, L2-resident)
__device__ __half g_xproj_h[VOCAB * UNITS];

// ---------------------------------------------------------------------------
// helpers
// ---------------------------------------------------------------------------
__device__ __forceinline__ uint32_t smem_u32(const void* p) {
    uint32_t a;
    asm("{ .reg .u64 t; cvta.to.shared.u64 t, %1; cvt.u32.u64 %0, t; }" : "=r"(a) : "l"(p));
    return a;
}
#define SWZ(off) ((uint32_t)(off) ^ ((((uint32_t)(off)) >> 3) & 0x70))

__device__ __forceinline__ uint32_t pack_f16(float lo, float hi) {
    uint32_t r; asm("cvt.rn.f16x2.f32 %0, %1, %2;" : "=r"(r) : "f"(hi), "f"(lo)); return r;
}
__device__ __forceinline__ uint32_t tanh2(uint32_t x) {
    uint32_t r; asm("tanh.approx.f16x2 %0, %1;" : "=r"(r) : "r"(x)); return r;
}
__device__ __forceinline__ float2 unpk_f16(uint32_t u) {
    __half2 h = *reinterpret_cast<__half2*>(&u);
    return __half22float2(h);
}

// LDSM: volatile (pins ordering) but no memory clobber.
#define LDSM_X4(r0, r1, r2, r3, addr)                                       \
    asm volatile("ldmatrix.sync.aligned.m8n8.x4.shared.b16 {%0,%1,%2,%3}, [%4];" \
                 : "=r"(r0), "=r"(r1), "=r"(r2), "=r"(r3) : "r"(addr))

// f16 C/D MMA, accumulate in place. Non-volatile pure register op.
#define MMA_F16C(ac, A, b0, b1)                                             \
    asm("mma.sync.aligned.m16n8k16.row.col.f16.f16.f16.f16 "                \
        "{%0,%1}, {%2,%3,%4,%5}, {%6,%7}, {%0,%1};"                         \
        : "+r"((ac)[0]), "+r"((ac)[1])                                      \
        : "r"((A)[0]), "r"((A)[1]), "r"((A)[2]), "r"((A)[3]),               \
          "r"(b0), "r"(b1))

#define CP_ASYNC_4(dst, src)                                                \
    asm volatile("cp.async.ca.shared.global [%0], [%1], 4;"                 \
                 :: "r"(dst), "l"(src) : "memory")
#define CP_COMMIT()  asm volatile("cp.async.commit_group;" ::: "memory")
#define CP_WAIT1()   asm volatile("cp.async.wait_group 1;" ::: "memory")
#define CP_WAIT0()   asm volatile("cp.async.wait_group 0;" ::: "memory")

// ---------------------------------------------------------------------------
// Kernel A: build xproj table (f16 output)
// ---------------------------------------------------------------------------
__global__ void build_xproj_kernel(const float* __restrict__ emb,
                                   const float* __restrict__ Wx1,
                                   const float* __restrict__ b1) {
    __shared__ float se[4 * EMBED];
    const int v0  = blockIdx.x * 4;
    const int tid = threadIdx.x;
    for (int i = tid; i < 4 * EMBED; i += 256)
        se[i] = emb[v0 * EMBED + i];
    __syncthreads();
    const int vl = tid >> 6;
    const int u  = tid & 63;
    const float* er = se + vl * EMBED;
    float a0 = 0.f, a1 = 0.f;
#pragma unroll
    for (int e = 0; e < EMBED; e += 2) {
        a0 += er[e]     * Wx1[e * UNITS + u];
        a1 += er[e + 1] * Wx1[(e + 1) * UNITS + u];
    }
    g_xproj_h[(v0 + vl) * UNITS + u] = __float2half(b1[u] + a0 + a1);
}

// ---------------------------------------------------------------------------
// smem layout (byte offsets from 1024-aligned base)
// ---------------------------------------------------------------------------
#define OFF_W1   0                                  // Wh1^T [n][k] f16 SW128, 8KB
#define OFF_W2   8192                               // Wh2^T [n][k] f16 SW128, 8KB
#define OFF_XS0  16384                              // xs buf 0: 128 rows x 144B
#define OFF_XS1  (OFF_XS0 + MROWS * XSB)
#define OFF_TOK  (OFF_XS1 + MROWS * XSB)            // 128 x 81 int
#define OFF_WD   (OFF_TOK + MROWS * TKS * 4)
#define SMEM_NEED (OFF_WD + 256 + 1024)

// ---------------------------------------------------------------------------
// Kernel B: 8 independent warps x 16 rows x 64 cols, full-f16 datapath.
// R12 structure with ONE delta: BH2 streamed from smem (W2 tile) instead of
// persistent registers → ~190 regs, scheduler freedom, no remat/spills.
// ---------------------------------------------------------------------------
__global__ void __launch_bounds__(256, 1)
rnn_mma_kernel(const int*   __restrict__ tokens,
               const float* __restrict__ Wh1,
               const float* __restrict__ Wx2,
               const float* __restrict__ Wh2,
               const float* __restrict__ b2,
               const float* __restrict__ Wd,
               const float* __restrict__ bd,
               float*       __restrict__ out) {
    extern __shared__ char dynsmem[];
    char* smem = (char*)(((uintptr_t)dynsmem + 1023) & ~(uintptr_t)1023);
    const uint32_t sb = smem_u32(smem);
    int*   stok = (int*)(smem + OFF_TOK);
    float* sWd  = (float*)(smem + OFF_WD);

    const int tid  = threadIdx.x;
    const int lane = tid & 31;
    const int wid  = tid >> 5;
    const int gid  = lane >> 2;
    const int tig  = lane & 3;
    const int wrow16 = wid * 16;
    const int m0   = blockIdx.x * MROWS;

    // ---- persistent Wx2 B-fragments (latency-critical gemm2b chain) ----
    uint32_t BX2[8][4][2];
#pragma unroll
    for (int nt = 0; nt < 8; nt++)
#pragma unroll
        for (int kt = 0; kt < 4; kt++) {
            const int n = nt * 8 + gid;
            const int k = kt * 16 + tig * 2;
            BX2[nt][kt][0] = pack_f16(Wx2[k * 64 + n],       Wx2[(k + 1) * 64 + n]);
            BX2[nt][kt][1] = pack_f16(Wx2[(k + 8) * 64 + n], Wx2[(k + 9) * 64 + n]);
        }
    // persistent b2 f16x2 (same pair for row g and g+8)
    uint32_t b2v[8];
#pragma unroll
    for (int nt = 0; nt < 8; nt++)
        b2v[nt] = pack_f16(b2[nt * 8 + tig * 2], b2[nt * 8 + tig * 2 + 1]);

    // ---- init smem: Wh1^T / Wh2^T tiles [n][k] f16 SW128, tokens, Wd ----
    for (int i = tid; i < UNITS * UNITS; i += 256) {
        int n = i >> 6, k = i & 63;
        uint32_t so = SWZ(n * 128 + k * 2);
        *(__half*)(smem + OFF_W1 + so) = __float2half(Wh1[k * 64 + n]);
        *(__half*)(smem + OFF_W2 + so) = __float2half(Wh2[k * 64 + n]);
    }
    {
        const int* gtok = tokens + m0 * SEQ;
        for (int i = tid; i < MROWS * SEQ; i += 256)
            stok[(i / SEQ) * TKS + (i % SEQ)] = gtok[i];
    }
    if (tid < UNITS) sWd[tid] = Wd[tid];
    __syncthreads();

    const uint32_t w1Base = sb + OFF_W1;
    const uint32_t w2Base = sb + OFF_W2;
    const uint32_t bRow = (uint32_t)((((lane >> 4) << 3) | (lane & 7)));
    const uint32_t bKo  = (uint32_t)(((lane >> 3) & 1) << 3);
    const uint32_t xsLaneOff = (uint32_t)(wrow16 * XSB) + (uint32_t)(lane * 4);

    // h fragments (A-frag layout, f16x2), h0 = 0
    uint32_t h1f[4][4], h2f[4][4];
#pragma unroll
    for (int kt = 0; kt < 4; kt++)
#pragma unroll
        for (int j = 0; j < 4; j++) { h1f[kt][j] = 0u; h2f[kt][j] = 0u; }

    uint32_t acc1[8][2], acc2[8][2];   // f16x2 accumulators

    // ---- prime gather pipeline: step 0 into buf 0 (4B/lane, 1 row/instr) ----
    {
        int tokreg = 0;
        if (lane < 16) tokreg = stok[(wrow16 + lane) * TKS + 0];
        const uint32_t dst = sb + OFF_XS0 + xsLaneOff;
#pragma unroll
        for (int r = 0; r < 16; r++) {
            const int tok = __shfl_sync(0xffffffffu, tokreg, r);
            CP_ASYNC_4(dst + (uint32_t)(r * XSB), g_xproj_h + tok * UNITS + lane * 2);
        }
        CP_COMMIT();
    }

    for (int t = 0; t < SEQ; t++) {
        const uint32_t xsOff = (t & 1) ? OFF_XS1 : OFF_XS0;

        // ---- prefetch gather for t+1; wait for step t's rows ----
        if (t + 1 < SEQ) {
            int tokreg = 0;
            if (lane < 16) tokreg = stok[(wrow16 + lane) * TKS + (t + 1)];
            const uint32_t dst = sb + (((t + 1) & 1) ? OFF_XS1 : OFF_XS0) + xsLaneOff;
#pragma unroll
            for (int r = 0; r < 16; r++) {
                const int tok = __shfl_sync(0xffffffffu, tokreg, r);
                CP_ASYNC_4(dst + (uint32_t)(r * XSB), g_xproj_h + tok * UNITS + lane * 2);
            }
            CP_COMMIT();
            CP_WAIT1();
        } else {
            CP_WAIT0();
        }

        // ---- init: acc1 = xproj(t) (f16x2 LDS, bank-conflict-free), acc2 = b2 ----
        {
            const char* xrow0 = smem + xsOff + (wrow16 + gid) * XSB + tig * 4;
#pragma unroll
            for (int nt = 0; nt < 8; nt++) {
                acc1[nt][0] = *(const uint32_t*)(xrow0 + nt * 16);
                acc1[nt][1] = *(const uint32_t*)(xrow0 + 8 * XSB + nt * 16);
                acc2[nt][0] = b2v[nt];
                acc2[nt][1] = b2v[nt];
            }
        }

        // ---- gemm1 (h1 @ Wh1) + gemm2a (h2 @ Wh2), both B streamed ----
#pragma unroll
        for (int kt = 0; kt < 4; kt++) {
            uint32_t Bs1[4][4], Bs2[4][4];
            const uint32_t so = SWZ((bRow) * 128 + (kt * 16 + bKo) * 2);
#pragma unroll
            for (int np = 0; np < 4; np++) {
                const uint32_t rel = SWZ((np * 16 + bRow) * 128 + (kt * 16 + bKo) * 2);
                LDSM_X4(Bs2[np][0], Bs2[np][1], Bs2[np][2], Bs2[np][3], w2Base + rel);
                LDSM_X4(Bs1[np][0], Bs1[np][1], Bs1[np][2], Bs1[np][3], w1Base + rel);
            }
            (void)so;
#pragma unroll
            for (int np = 0; np < 4; np++) {
                MMA_F16C(acc2[2 * np],     h2f[kt], Bs2[np][0], Bs2[np][1]);
                MMA_F16C(acc2[2 * np + 1], h2f[kt], Bs2[np][2], Bs2[np][3]);
            }
#pragma unroll
            for (int np = 0; np < 4; np++) {
                MMA_F16C(acc1[2 * np],     h1f[kt], Bs1[np][0], Bs1[np][1]);
                MMA_F16C(acc1[2 * np + 1], h1f[kt], Bs1[np][2], Bs1[np][3]);
            }
        }

        // ---- epi1: h1 = tanh2(acc1) — accumulator IS the next A-frag ----
#pragma unroll
        for (int nt = 0; nt < 8; nt++) {
            h1f[nt >> 1][(nt & 1) * 2 + 0] = tanh2(acc1[nt][0]);
            h1f[nt >> 1][(nt & 1) * 2 + 1] = tanh2(acc1[nt][1]);
        }

        // ---- gemm2b: acc2 += h1_new @ Wx2 (register B-frags) ----
#pragma unroll
        for (int kt = 0; kt < 4; kt++)
#pragma unroll
            for (int nt = 0; nt < 8; nt++)
                MMA_F16C(acc2[nt], h1f[kt], BX2[nt][kt][0], BX2[nt][kt][1]);

        // ---- epi2: h2 = tanh2(acc2) ----
#pragma unroll
        for (int nt = 0; nt < 8; nt++) {
            h2f[nt >> 1][(nt & 1) * 2 + 0] = tanh2(acc2[nt][0]);
            h2f[nt >> 1][(nt & 1) * 2 + 1] = tanh2(acc2[nt][1]);
        }
    }

    // ---- head: out = sigmoid(h2 . Wd + bd); reduce over tig group ----
    float z0 = 0.f, z1 = 0.f;
#pragma unroll
    for (int nt = 0; nt < 8; nt++) {
        const int col = nt * 8 + tig * 2;
        float2 wd = *(const float2*)(sWd + col);
        float2 a = unpk_f16(h2f[nt >> 1][(nt & 1) * 2 + 0]);   // row gid
        float2 b = unpk_f16(h2f[nt >> 1][(nt & 1) * 2 + 1]);   // row gid+8
        z0 += a.x * wd.x + a.y * wd.y;
        z1 += b.x * wd.x + b.y * wd.y;
    }
    z0 += __shfl_xor_sync(0xffffffffu, z0, 1);
    z0 += __shfl_xor_sync(0xffffffffu, z0, 2);
    z1 += __shfl_xor_sync(0xffffffffu, z1, 1);
    z1 += __shfl_xor_sync(0xffffffffu, z1, 2);
    if (tig == 0) {
        const float bd0 = bd[0];
        out[m0 + wrow16 + gid]     = 1.0f / (1.0f + __expf(-(z0 + bd0)));
        out[m0 + wrow16 + gid + 8] = 1.0f / (1.0f + __expf(-(z1 + bd0)));
    }
}

// ---------------------------------------------------------------------------
extern "C" void kernel_launch(void* const* d_in, const int* in_sizes, int n_in,
                              void* d_out, int out_size) {
    const int*   tokens = (const int*)  d_in[0];
    const float* emb    = (const float*)d_in[1];
    const float* Wx1    = (const float*)d_in[2];
    const float* Wh1    = (const float*)d_in[3];
    const float* b1     = (const float*)d_in[4];
    const float* Wx2    = (const float*)d_in[5];
    const float* Wh2    = (const float*)d_in[6];
    const float* b2     = (const float*)d_in[7];
    const float* Wd     = (const float*)d_in[8];
    const float* bd     = (const float*)d_in[9];
    float* out = (float*)d_out;

    build_xproj_kernel<<<VOCAB / 4, 256>>>(emb, Wx1, b1);

    cudaFuncSetAttribute(rnn_mma_kernel,
                         cudaFuncAttributeMaxDynamicSharedMemorySize, SMEM_NEED);
    rnn_mma_kernel<<<BATCH / MROWS, 256, SMEM_NEED>>>(
        tokens, Wh1, Wx2, Wh2, b2, Wd, bd, out);
}

// round 17
// speedup vs baseline: 1.2532x; 1.0169x over previous
#include <cuda_runtime.h>
#include <cuda_fp16.h>
#include <cstdint>

#define VOCAB 10000
#define EMBED 100
#define SEQ   80
#define UNITS 64
#define BATCH 16384
#define MROWS 128          // batch rows per CTA
#define XSB   144          // xs row stride BYTES (conflict-free init)
#define TKS   81           // token smem row stride (ints)

// xproj[v][u] = b1[u] + emb[v,:] @ Wx1[:,u]   (f16, 1.28 MB, L2-resident)
__device__ __half g_xproj_h[VOCAB * UNITS];

// ---------------------------------------------------------------------------
// helpers
// ---------------------------------------------------------------------------
__device__ __forceinline__ uint32_t smem_u32(const void* p) {
    uint32_t a;
    asm("{ .reg .u64 t; cvta.to.shared.u64 t, %1; cvt.u32.u64 %0, t; }" : "=r"(a) : "l"(p));
    return a;
}
#define SWZ(off) ((uint32_t)(off) ^ ((((uint32_t)(off)) >> 3) & 0x70))

__device__ __forceinline__ uint32_t pack_f16(float lo, float hi) {
    uint32_t r; asm("cvt.rn.f16x2.f32 %0, %1, %2;" : "=r"(r) : "f"(hi), "f"(lo)); return r;
}
__device__ __forceinline__ uint32_t tanh2(uint32_t x) {
    uint32_t r; asm("tanh.approx.f16x2 %0, %1;" : "=r"(r) : "r"(x)); return r;
}
__device__ __forceinline__ float2 unpk_f16(uint32_t u) {
    __half2 h = *reinterpret_cast<__half2*>(&u);
    return __half22float2(h);
}

// LDSM: volatile (pins ordering) but no memory clobber.
#define LDSM_X4(r0, r1, r2, r3, addr)                                       \
    asm volatile("ldmatrix.sync.aligned.m8n8.x4.shared.b16 {%0,%1,%2,%3}, [%4];" \
                 : "=r"(r0), "=r"(r1), "=r"(r2), "=r"(r3) : "r"(addr))

// f16 C/D MMA, accumulate in place. Non-volatile pure register op.
#define MMA_F16C(ac, A, b0, b1)                                             \
    asm("mma.sync.aligned.m16n8k16.row.col.f16.f16.f16.f16 "                \
        "{%0,%1}, {%2,%3,%4,%5}, {%6,%7}, {%0,%1};"                         \
        : "+r"((ac)[0]), "+r"((ac)[1])                                      \
        : "r"((A)[0]), "r"((A)[1]), "r"((A)[2]), "r"((A)[3]),               \
          "r"(b0), "r"(b1))

#define CP_ASYNC_4(dst, src)                                                \
    asm volatile("cp.async.ca.shared.global [%0], [%1], 4;"                 \
                 :: "r"(dst), "l"(src) : "memory")
#define CP_COMMIT()  asm volatile("cp.async.commit_group;" ::: "memory")
#define CP_WAIT1()   asm volatile("cp.async.wait_group 1;" ::: "memory")
#define CP_WAIT0()   asm volatile("cp.async.wait_group 0;" ::: "memory")

// ---------------------------------------------------------------------------
// Kernel A: build xproj table (f16 output)
// ---------------------------------------------------------------------------
__global__ void build_xproj_kernel(const float* __restrict__ emb,
                                   const float* __restrict__ Wx1,
                                   const float* __restrict__ b1) {
    __shared__ float se[4 * EMBED];
    const int v0  = blockIdx.x * 4;
    const int tid = threadIdx.x;
    for (int i = tid; i < 4 * EMBED; i += 256)
        se[i] = emb[v0 * EMBED + i];
    __syncthreads();
    const int vl = tid >> 6;
    const int u  = tid & 63;
    const float* er = se + vl * EMBED;
    float a0 = 0.f, a1 = 0.f;
#pragma unroll
    for (int e = 0; e < EMBED; e += 2) {
        a0 += er[e]     * Wx1[e * UNITS + u];
        a1 += er[e + 1] * Wx1[(e + 1) * UNITS + u];
    }
    g_xproj_h[(v0 + vl) * UNITS + u] = __float2half(b1[u] + a0 + a1);
}

// ---------------------------------------------------------------------------
// smem layout (byte offsets from 1024-aligned base)
// ---------------------------------------------------------------------------
#define OFF_W1   0                                  // Wh1^T [n][k] f16 SW128, 8KB
#define OFF_W2   8192                               // Wh2^T [n][k] f16 SW128, 8KB
#define OFF_XS0  16384                              // xs buf 0: 128 rows x 144B
#define OFF_XS1  (OFF_XS0 + MROWS * XSB)
#define OFF_TOK  (OFF_XS1 + MROWS * XSB)            // 128 x 81 int
#define OFF_WD   (OFF_TOK + MROWS * TKS * 4)
#define SMEM_NEED (OFF_WD + 256 + 1024)

// ---------------------------------------------------------------------------
// Kernel B: 8 independent warps x 16 rows x 64 cols, full-f16 datapath.
// R16 + hoisted LDSM addresses (32 regs) + t-loop unroll x2 (cross-step
// overlap — now with real register slack).
// ---------------------------------------------------------------------------
__global__ void __launch_bounds__(256, 1)
rnn_mma_kernel(const int*   __restrict__ tokens,
               const float* __restrict__ Wh1,
               const float* __restrict__ Wx2,
               const float* __restrict__ Wh2,
               const float* __restrict__ b2,
               const float* __restrict__ Wd,
               const float* __restrict__ bd,
               float*       __restrict__ out) {
    extern __shared__ char dynsmem[];
    char* smem = (char*)(((uintptr_t)dynsmem + 1023) & ~(uintptr_t)1023);
    const uint32_t sb = smem_u32(smem);
    int*   stok = (int*)(smem + OFF_TOK);
    float* sWd  = (float*)(smem + OFF_WD);

    const int tid  = threadIdx.x;
    const int lane = tid & 31;
    const int wid  = tid >> 5;
    const int gid  = lane >> 2;
    const int tig  = lane & 3;
    const int wrow16 = wid * 16;
    const int m0   = blockIdx.x * MROWS;

    // ---- persistent Wx2 B-fragments (latency-critical gemm2b chain) ----
    uint32_t BX2[8][4][2];
#pragma unroll
    for (int nt = 0; nt < 8; nt++)
#pragma unroll
        for (int kt = 0; kt < 4; kt++) {
            const int n = nt * 8 + gid;
            const int k = kt * 16 + tig * 2;
            BX2[nt][kt][0] = pack_f16(Wx2[k * 64 + n],       Wx2[(k + 1) * 64 + n]);
            BX2[nt][kt][1] = pack_f16(Wx2[(k + 8) * 64 + n], Wx2[(k + 9) * 64 + n]);
        }
    // persistent b2 f16x2 (same pair for row g and g+8)
    uint32_t b2v[8];
#pragma unroll
    for (int nt = 0; nt < 8; nt++)
        b2v[nt] = pack_f16(b2[nt * 8 + tig * 2], b2[nt * 8 + tig * 2 + 1]);

    // ---- init smem: Wh1^T / Wh2^T tiles [n][k] f16 SW128, tokens, Wd ----
    for (int i = tid; i < UNITS * UNITS; i += 256) {
        int n = i >> 6, k = i & 63;
        uint32_t so = SWZ(n * 128 + k * 2);
        *(__half*)(smem + OFF_W1 + so) = __float2half(Wh1[k * 64 + n]);
        *(__half*)(smem + OFF_W2 + so) = __float2half(Wh2[k * 64 + n]);
    }
    {
        const int* gtok = tokens + m0 * SEQ;
        for (int i = tid; i < MROWS * SEQ; i += 256)
            stok[(i / SEQ) * TKS + (i % SEQ)] = gtok[i];
    }
    if (tid < UNITS) sWd[tid] = Wd[tid];
    __syncthreads();

    const uint32_t bRow = (uint32_t)((((lane >> 4) << 3) | (lane & 7)));
    const uint32_t bKo  = (uint32_t)(((lane >> 3) & 1) << 3);
    const uint32_t xsLaneOff = (uint32_t)(wrow16 * XSB) + (uint32_t)(lane * 4);

    // ---- hoisted LDSM addresses: 32 regs, loop-invariant ----
    uint32_t a1Addr[4][4], a2Addr[4][4];
#pragma unroll
    for (int kt = 0; kt < 4; kt++)
#pragma unroll
        for (int np = 0; np < 4; np++) {
            const uint32_t rel = SWZ((np * 16 + bRow) * 128 + (kt * 16 + bKo) * 2);
            a1Addr[kt][np] = sb + OFF_W1 + rel;
            a2Addr[kt][np] = sb + OFF_W2 + rel;
        }

    // h fragments (A-frag layout, f16x2), h0 = 0
    uint32_t h1f[4][4], h2f[4][4];
#pragma unroll
    for (int kt = 0; kt < 4; kt++)
#pragma unroll
        for (int j = 0; j < 4; j++) { h1f[kt][j] = 0u; h2f[kt][j] = 0u; }

    uint32_t acc1[8][2], acc2[8][2];   // f16x2 accumulators

    // ---- prime gather pipeline: step 0 into buf 0 (4B/lane, 1 row/instr) ----
    {
        int tokreg = 0;
        if (lane < 16) tokreg = stok[(wrow16 + lane) * TKS + 0];
        const uint32_t dst = sb + OFF_XS0 + xsLaneOff;
#pragma unroll
        for (int r = 0; r < 16; r++) {
            const int tok = __shfl_sync(0xffffffffu, tokreg, r);
            CP_ASYNC_4(dst + (uint32_t)(r * XSB), g_xproj_h + tok * UNITS + lane * 2);
        }
        CP_COMMIT();
    }

#pragma unroll 2
    for (int t = 0; t < SEQ; t++) {
        const uint32_t xsOff = (t & 1) ? OFF_XS1 : OFF_XS0;

        // ---- prefetch gather for t+1; wait for step t's rows ----
        if (t + 1 < SEQ) {
            int tokreg = 0;
            if (lane < 16) tokreg = stok[(wrow16 + lane) * TKS + (t + 1)];
            const uint32_t dst = sb + (((t + 1) & 1) ? OFF_XS1 : OFF_XS0) + xsLaneOff;
#pragma unroll
            for (int r = 0; r < 16; r++) {
                const int tok = __shfl_sync(0xffffffffu, tokreg, r);
                CP_ASYNC_4(dst + (uint32_t)(r * XSB), g_xproj_h + tok * UNITS + lane * 2);
            }
            CP_COMMIT();
            CP_WAIT1();
        } else {
            CP_WAIT0();
        }

        // ---- init: acc1 = xproj(t) (f16x2 LDS, bank-conflict-free), acc2 = b2 ----
        {
            const char* xrow0 = smem + xsOff + (wrow16 + gid) * XSB + tig * 4;
#pragma unroll
            for (int nt = 0; nt < 8; nt++) {
                acc1[nt][0] = *(const uint32_t*)(xrow0 + nt * 16);
                acc1[nt][1] = *(const uint32_t*)(xrow0 + 8 * XSB + nt * 16);
                acc2[nt][0] = b2v[nt];
                acc2[nt][1] = b2v[nt];
            }
        }

        // ---- gemm1 (h1 @ Wh1) + gemm2a (h2 @ Wh2), both B streamed ----
#pragma unroll
        for (int kt = 0; kt < 4; kt++) {
            uint32_t Bs1[4][4], Bs2[4][4];
#pragma unroll
            for (int np = 0; np < 4; np++) {
                LDSM_X4(Bs2[np][0], Bs2[np][1], Bs2[np][2], Bs2[np][3], a2Addr[kt][np]);
                LDSM_X4(Bs1[np][0], Bs1[np][1], Bs1[np][2], Bs1[np][3], a1Addr[kt][np]);
            }
#pragma unroll
            for (int np = 0; np < 4; np++) {
                MMA_F16C(acc2[2 * np],     h2f[kt], Bs2[np][0], Bs2[np][1]);
                MMA_F16C(acc2[2 * np + 1], h2f[kt], Bs2[np][2], Bs2[np][3]);
            }
#pragma unroll
            for (int np = 0; np < 4; np++) {
                MMA_F16C(acc1[2 * np],     h1f[kt], Bs1[np][0], Bs1[np][1]);
                MMA_F16C(acc1[2 * np + 1], h1f[kt], Bs1[np][2], Bs1[np][3]);
            }
        }

        // ---- epi1: h1 = tanh2(acc1) — accumulator IS the next A-frag ----
#pragma unroll
        for (int nt = 0; nt < 8; nt++) {
            h1f[nt >> 1][(nt & 1) * 2 + 0] = tanh2(acc1[nt][0]);
            h1f[nt >> 1][(nt & 1) * 2 + 1] = tanh2(acc1[nt][1]);
        }

        // ---- gemm2b: acc2 += h1_new @ Wx2 (register B-frags) ----
#pragma unroll
        for (int kt = 0; kt < 4; kt++)
#pragma unroll
            for (int nt = 0; nt < 8; nt++)
                MMA_F16C(acc2[nt], h1f[kt], BX2[nt][kt][0], BX2[nt][kt][1]);

        // ---- epi2: h2 = tanh2(acc2) ----
#pragma unroll
        for (int nt = 0; nt < 8; nt++) {
            h2f[nt >> 1][(nt & 1) * 2 + 0] = tanh2(acc2[nt][0]);
            h2f[nt >> 1][(nt & 1) * 2 + 1] = tanh2(acc2[nt][1]);
        }
    }

    // ---- head: out = sigmoid(h2 . Wd + bd); reduce over tig group ----
    float z0 = 0.f, z1 = 0.f;
#pragma unroll
    for (int nt = 0; nt < 8; nt++) {
        const int col = nt * 8 + tig * 2;
        float2 wd = *(const float2*)(sWd + col);
        float2 a = unpk_f16(h2f[nt >> 1][(nt & 1) * 2 + 0]);   // row gid
        float2 b = unpk_f16(h2f[nt >> 1][(nt & 1) * 2 + 1]);   // row gid+8
        z0 += a.x * wd.x + a.y * wd.y;
        z1 += b.x * wd.x + b.y * wd.y;
    }
    z0 += __shfl_xor_sync(0xffffffffu, z0, 1);
    z0 += __shfl_xor_sync(0xffffffffu, z0, 2);
    z1 += __shfl_xor_sync(0xffffffffu, z1, 1);
    z1 += __shfl_xor_sync(0xffffffffu, z1, 2);
    if (tig == 0) {
        const float bd0 = bd[0];
        out[m0 + wrow16 + gid]     = 1.0f / (1.0f + __expf(-(z0 + bd0)));
        out[m0 + wrow16 + gid + 8] = 1.0f / (1.0f + __expf(-(z1 + bd0)));
    }
}

// ---------------------------------------------------------------------------
extern "C" void kernel_launch(void* const* d_in, const int* in_sizes, int n_in,
                              void* d_out, int out_size) {
    const int*   tokens = (const int*)  d_in[0];
    const float* emb    = (const float*)d_in[1];
    const float* Wx1    = (const float*)d_in[2];
    const float* Wh1    = (const float*)d_in[3];
    const float* b1     = (const float*)d_in[4];
    const float* Wx2    = (const float*)d_in[5];
    const float* Wh2    = (const float*)d_in[6];
    const float* b2     = (const float*)d_in[7];
    const float* Wd     = (const float*)d_in[8];
    const float* bd     = (const float*)d_in[9];
    float* out = (float*)d_out;

    build_xproj_kernel<<<VOCAB / 4, 256>>>(emb, Wx1, b1);

    cudaFuncSetAttribute(rnn_mma_kernel,
                         cudaFuncAttributeMaxDynamicSharedMemorySize, SMEM_NEED);
    rnn_mma_kernel<<<BATCH / MROWS, 256, SMEM_NEED>>>(
        tokens, Wh1, Wx2, Wh2, b2, Wd, bd, out);
}